// round 1
// baseline (speedup 1.0000x reference)
#include <cuda_runtime.h>
#include <math.h>

// Problem dims (fixed by the reference)
#define BB 2
#define SS 1024
#define DD 1024
#define HH 16
#define DKK 64
#define FF 4096
#define LL 6
#define ROWS (BB*SS)   // 2048

// ---------------- scratch (static device globals; no allocs allowed) -------
__device__ float g_x  [ROWS*DD];            // residual stream
__device__ float g_h  [ROWS*DD];            // LN output
__device__ float g_q  [ROWS*DD];
__device__ float g_k  [ROWS*DD];
__device__ float g_v  [ROWS*DD];
__device__ float g_att[ROWS*DD];            // attention output pre-Wo
__device__ float g_scores[(long long)BB*HH*SS*SS]; // 128 MB
__device__ float g_ff [ROWS*FF];            // 32 MB

// ---------------- reductions ----------------
__device__ __forceinline__ float block_reduce_sum(float v) {
    __shared__ float sh[32];
    int lane = threadIdx.x & 31, wid = threadIdx.x >> 5;
    #pragma unroll
    for (int o = 16; o > 0; o >>= 1) v += __shfl_down_sync(0xffffffff, v, o);
    if (lane == 0) sh[wid] = v;
    __syncthreads();
    float r = 0.f;
    if (wid == 0) {
        r = (lane < (blockDim.x >> 5)) ? sh[lane] : 0.f;
        #pragma unroll
        for (int o = 16; o > 0; o >>= 1) r += __shfl_down_sync(0xffffffff, r, o);
        if (lane == 0) sh[0] = r;
    }
    __syncthreads();
    r = sh[0];
    __syncthreads();
    return r;
}

__device__ __forceinline__ float block_reduce_max(float v) {
    __shared__ float sh[32];
    int lane = threadIdx.x & 31, wid = threadIdx.x >> 5;
    #pragma unroll
    for (int o = 16; o > 0; o >>= 1) v = fmaxf(v, __shfl_down_sync(0xffffffff, v, o));
    if (lane == 0) sh[wid] = v;
    __syncthreads();
    float r = -3.4e38f;
    if (wid == 0) {
        r = (lane < (blockDim.x >> 5)) ? sh[lane] : -3.4e38f;
        #pragma unroll
        for (int o = 16; o > 0; o >>= 1) r = fmaxf(r, __shfl_down_sync(0xffffffff, r, o));
        if (lane == 0) sh[0] = r;
    }
    __syncthreads();
    r = sh[0];
    __syncthreads();
    return r;
}

// ---------------- embed: x = emb[ids]*sqrt(D) + pe ----------------
__global__ void te_embed_kernel(const int* __restrict__ ids,
                                const float* __restrict__ emb,
                                const float* __restrict__ pe) {
    int row = blockIdx.x;          // 0..2047  (b*S + s)
    int s = row & (SS - 1);
    int id = ids[row];
    const float* e = emb + (long long)id * DD;
    const float* p = pe + (long long)s * DD;
    float* x = g_x + (long long)row * DD;
    for (int j = threadIdx.x; j < DD; j += blockDim.x)
        x[j] = e[j] * 32.0f + p[j];   // sqrt(1024)=32
}

// ---------------- layernorm ----------------
__global__ void te_ln_kernel(const float* __restrict__ in,
                             float* __restrict__ out,
                             const float* __restrict__ gamma,
                             const float* __restrict__ beta) {
    int row = blockIdx.x;
    const float* x = in + (long long)row * DD;
    float s = 0.f, sq = 0.f;
    for (int j = threadIdx.x; j < DD; j += blockDim.x) {
        float v = x[j];
        s += v; sq += v * v;
    }
    s  = block_reduce_sum(s);
    sq = block_reduce_sum(sq);
    float mean = s * (1.0f / DD);
    float var  = sq * (1.0f / DD) - mean * mean;
    float inv  = rsqrtf(var + 1e-6f);
    float* o = out + (long long)row * DD;
    for (int j = threadIdx.x; j < DD; j += blockDim.x)
        o[j] = (x[j] - mean) * inv * gamma[j] + beta[j];
}

// ---------------- softmax over scores rows (with mask) ----------------
__global__ void te_softmax_kernel(const float* __restrict__ mask) {
    long long row = blockIdx.x;            // 0..B*H*S-1
    int b = (int)(row / (HH * SS));
    float* sc = g_scores + row * SS;
    const float* mrow = mask + (long long)b * SS;

    float mx = -3.4e38f;
    for (int k = threadIdx.x; k < SS; k += blockDim.x) {
        float v = sc[k];
        if (mrow[k] == 0.0f) { v = -1e9f; sc[k] = v; }
        mx = fmaxf(mx, v);
    }
    mx = block_reduce_max(mx);
    float sum = 0.f;
    for (int k = threadIdx.x; k < SS; k += blockDim.x) {
        float e = expf(sc[k] - mx);
        sc[k] = e;
        sum += e;
    }
    sum = block_reduce_sum(sum);
    float inv = 1.0f / sum;
    for (int k = threadIdx.x; k < SS; k += blockDim.x)
        sc[k] *= inv;
}

// ---------------- generic tiled SGEMM ----------------
// C[z] = alpha * A[z] @ op(B[z]) (+bias) (relu) (+resid), per batch index z.
// op(B) = B         (TRANSB=false): B is K x N, ldb = row stride
// op(B) = B^T       (TRANSB=true) : B is N x K, ldb = row stride
#define BM 128
#define BN 128
#define BK 8
#define TM 8
#define TN 8

template<bool TRANSB>
__global__ void __launch_bounds__(256)
te_sgemm_kernel(int M, int N, int K,
                const float* __restrict__ A, int lda, long long bsA,
                const float* __restrict__ Bm, int ldb, long long bsB,
                float* __restrict__ C, int ldc, long long bsC,
                const float* __restrict__ bias,
                const float* __restrict__ resid, int ldr, long long bsR,
                float alpha, int relu) {
    A  += (long long)blockIdx.z * bsA;
    Bm += (long long)blockIdx.z * bsB;
    C  += (long long)blockIdx.z * bsC;
    if (resid) resid += (long long)blockIdx.z * bsR;

    __shared__ float As[BK][BM];
    __shared__ float Bs[BK][BN];

    const int t = threadIdx.x;
    const int rowBase = blockIdx.y * BM;
    const int colBase = blockIdx.x * BN;
    const int tx = t & 15;         // 16 thread-cols
    const int ty = t >> 4;         // 16 thread-rows

    float acc[TM][TN];
    #pragma unroll
    for (int i = 0; i < TM; i++)
        #pragma unroll
        for (int j = 0; j < TN; j++) acc[i][j] = 0.f;

    for (int kt = 0; kt < K; kt += BK) {
        // load A tile: BM x BK (stored transposed As[k][m])
        #pragma unroll
        for (int i = 0; i < 4; i++) {
            int lin = t + i * 256;
            int r = lin >> 3;
            int c = lin & 7;
            int gr = rowBase + r, gc = kt + c;
            As[c][r] = (gr < M && gc < K) ? A[(long long)gr * lda + gc] : 0.f;
        }
        // load B tile: BK x BN
        if (TRANSB) {
            #pragma unroll
            for (int i = 0; i < 4; i++) {
                int lin = t + i * 256;
                int r = lin & 7;        // k
                int c = lin >> 3;       // n
                int gk = kt + r, gn = colBase + c;
                Bs[r][c] = (gk < K && gn < N) ? Bm[(long long)gn * ldb + gk] : 0.f;
            }
        } else {
            #pragma unroll
            for (int i = 0; i < 4; i++) {
                int lin = t + i * 256;
                int r = lin >> 7;       // k
                int c = lin & 127;      // n
                int gk = kt + r, gn = colBase + c;
                Bs[r][c] = (gk < K && gn < N) ? Bm[(long long)gk * ldb + gn] : 0.f;
            }
        }
        __syncthreads();

        #pragma unroll
        for (int kk = 0; kk < BK; kk++) {
            float a[TM], b[TN];
            #pragma unroll
            for (int i = 0; i < TM; i++) a[i] = As[kk][ty * TM + i];
            #pragma unroll
            for (int j = 0; j < TN; j++) b[j] = Bs[kk][tx * TN + j];
            #pragma unroll
            for (int i = 0; i < TM; i++)
                #pragma unroll
                for (int j = 0; j < TN; j++)
                    acc[i][j] = fmaf(a[i], b[j], acc[i][j]);
        }
        __syncthreads();
    }

    #pragma unroll
    for (int i = 0; i < TM; i++) {
        int gm = rowBase + ty * TM + i;
        if (gm >= M) continue;
        #pragma unroll
        for (int j = 0; j < TN; j++) {
            int gn = colBase + tx * TN + j;
            if (gn >= N) continue;
            float v = acc[i][j] * alpha;
            if (bias)  v += bias[gn];
            if (relu)  v = fmaxf(v, 0.f);
            if (resid) v += resid[(long long)gm * ldr + gn];
            C[(long long)gm * ldc + gn] = v;
        }
    }
}

// ---------------- host launch ----------------
extern "C" void kernel_launch(void* const* d_in, const int* in_sizes, int n_in,
                              void* d_out, int out_size) {
    const int*   ids    = (const int*)  d_in[0];
    const float* amask  = (const float*)d_in[1];
    const float* emb    = (const float*)d_in[2];
    const float* pe     = (const float*)d_in[3];
    const float* w_q    = (const float*)d_in[4];
    const float* w_k    = (const float*)d_in[5];
    const float* w_v    = (const float*)d_in[6];
    const float* w_o    = (const float*)d_in[7];
    const float* b_o    = (const float*)d_in[8];
    const float* w1     = (const float*)d_in[9];
    const float* b1     = (const float*)d_in[10];
    const float* w2     = (const float*)d_in[11];
    const float* b2     = (const float*)d_in[12];
    const float* ln1_s  = (const float*)d_in[13];
    const float* ln1_b  = (const float*)d_in[14];
    const float* ln2_s  = (const float*)d_in[15];
    const float* ln2_b  = (const float*)d_in[16];
    const float* lnf_s  = (const float*)d_in[17];
    const float* lnf_b  = (const float*)d_in[18];
    float* out = (float*)d_out;

    // device symbol addresses
    float *px, *ph, *pq, *pk, *pv, *patt, *psc, *pff;
    cudaGetSymbolAddress((void**)&px,  g_x);
    cudaGetSymbolAddress((void**)&ph,  g_h);
    cudaGetSymbolAddress((void**)&pq,  g_q);
    cudaGetSymbolAddress((void**)&pk,  g_k);
    cudaGetSymbolAddress((void**)&pv,  g_v);
    cudaGetSymbolAddress((void**)&patt,g_att);
    cudaGetSymbolAddress((void**)&psc, g_scores);
    cudaGetSymbolAddress((void**)&pff, g_ff);

    te_embed_kernel<<<ROWS, 256>>>(ids, emb, pe);

    for (int l = 0; l < LL; l++) {
        const float* wq  = w_q + (long long)l * DD * DD;
        const float* wk  = w_k + (long long)l * DD * DD;
        const float* wv  = w_v + (long long)l * DD * DD;
        const float* wo  = w_o + (long long)l * DD * DD;
        const float* bo  = b_o + (long long)l * DD;
        const float* W1  = w1  + (long long)l * DD * FF;
        const float* B1  = b1  + (long long)l * FF;
        const float* W2  = w2  + (long long)l * FF * DD;
        const float* B2  = b2  + (long long)l * DD;

        // LN1
        te_ln_kernel<<<ROWS, 256>>>(px, ph, ln1_s + (long long)l*DD, ln1_b + (long long)l*DD);

        // Q, K, V projections: (2048,1024) @ (1024,1024)
        dim3 gProj(DD / BN, ROWS / BM, 1);
        te_sgemm_kernel<false><<<gProj, 256>>>(ROWS, DD, DD, ph, DD, 0, wq, DD, 0,
                                               pq, DD, 0, nullptr, nullptr, 0, 0, 1.f, 0);
        te_sgemm_kernel<false><<<gProj, 256>>>(ROWS, DD, DD, ph, DD, 0, wk, DD, 0,
                                               pk, DD, 0, nullptr, nullptr, 0, 0, 1.f, 0);
        te_sgemm_kernel<false><<<gProj, 256>>>(ROWS, DD, DD, ph, DD, 0, wv, DD, 0,
                                               pv, DD, 0, nullptr, nullptr, 0, 0, 1.f, 0);

        // scores[b,h] = q_bh @ k_bh^T / 8 ;  per b, batch over heads (z)
        for (int b = 0; b < BB; b++) {
            dim3 gSc(SS / BN, SS / BM, HH);
            te_sgemm_kernel<true><<<gSc, 256>>>(SS, SS, DKK,
                pq + (long long)b * SS * DD, DD, DKK,
                pk + (long long)b * SS * DD, DD, DKK,
                psc + (long long)b * HH * SS * SS, SS, (long long)SS * SS,
                nullptr, nullptr, 0, 0, 0.125f, 0);
        }

        te_softmax_kernel<<<BB * HH * SS, 256>>>(amask);

        // attn @ v : per b, batch over heads
        for (int b = 0; b < BB; b++) {
            dim3 gAv((DKK + BN - 1) / BN, SS / BM, HH);
            te_sgemm_kernel<false><<<gAv, 256>>>(SS, DKK, SS,
                psc + (long long)b * HH * SS * SS, SS, (long long)SS * SS,
                pv + (long long)b * SS * DD, DD, DKK,
                patt + (long long)b * SS * DD, DD, DKK,
                nullptr, nullptr, 0, 0, 1.f, 0);
        }

        // Wo projection + bias + residual -> x (in place, element-local)
        te_sgemm_kernel<false><<<gProj, 256>>>(ROWS, DD, DD, patt, DD, 0, wo, DD, 0,
                                               px, DD, 0, bo, px, DD, 0, 1.f, 0);

        // LN2
        te_ln_kernel<<<ROWS, 256>>>(px, ph, ln2_s + (long long)l*DD, ln2_b + (long long)l*DD);

        // FF1: relu(h @ W1 + B1)
        dim3 gF1(FF / BN, ROWS / BM, 1);
        te_sgemm_kernel<false><<<gF1, 256>>>(ROWS, FF, DD, ph, DD, 0, W1, FF, 0,
                                             pff, FF, 0, B1, nullptr, 0, 0, 1.f, 1);
        // FF2: ff @ W2 + B2 + residual -> x
        dim3 gF2(DD / BN, ROWS / BM, 1);
        te_sgemm_kernel<false><<<gF2, 256>>>(ROWS, DD, FF, pff, FF, 0, W2, DD, 0,
                                             px, DD, 0, B2, px, DD, 0, 1.f, 0);
    }

    // final LN -> out
    te_ln_kernel<<<ROWS, 256>>>(px, out, lnf_s, lnf_b);
}

// round 2
// speedup vs baseline: 3.4349x; 3.4349x over previous
#include <cuda_runtime.h>
#include <math.h>
#include <stdint.h>

// Problem dims (fixed by the reference)
#define BB 2
#define SS 1024
#define DD 1024
#define HH 16
#define DKK 64
#define FF 4096
#define LL 6
#define ROWS (BB*SS)   // 2048

// ---------------- scratch (static device globals; no allocs allowed) -------
__device__ float g_x  [ROWS*DD];            // residual stream
__device__ float g_h  [ROWS*DD];            // LN output
__device__ float g_q  [ROWS*DD];
__device__ float g_k  [ROWS*DD];
__device__ float g_v  [ROWS*DD];
__device__ float g_att[ROWS*DD];            // attention output pre-Wo
__device__ float g_scores[(long long)BB*HH*SS*SS]; // 128 MB
__device__ float g_ff [ROWS*FF];            // 32 MB

// ---------------- reductions ----------------
__device__ __forceinline__ float block_reduce_sum(float v) {
    __shared__ float sh[32];
    int lane = threadIdx.x & 31, wid = threadIdx.x >> 5;
    #pragma unroll
    for (int o = 16; o > 0; o >>= 1) v += __shfl_down_sync(0xffffffff, v, o);
    if (lane == 0) sh[wid] = v;
    __syncthreads();
    float r = 0.f;
    if (wid == 0) {
        r = (lane < (blockDim.x >> 5)) ? sh[lane] : 0.f;
        #pragma unroll
        for (int o = 16; o > 0; o >>= 1) r += __shfl_down_sync(0xffffffff, r, o);
        if (lane == 0) sh[0] = r;
    }
    __syncthreads();
    r = sh[0];
    __syncthreads();
    return r;
}

__device__ __forceinline__ float block_reduce_max(float v) {
    __shared__ float sh[32];
    int lane = threadIdx.x & 31, wid = threadIdx.x >> 5;
    #pragma unroll
    for (int o = 16; o > 0; o >>= 1) v = fmaxf(v, __shfl_down_sync(0xffffffff, v, o));
    if (lane == 0) sh[wid] = v;
    __syncthreads();
    float r = -3.4e38f;
    if (wid == 0) {
        r = (lane < (blockDim.x >> 5)) ? sh[lane] : -3.4e38f;
        #pragma unroll
        for (int o = 16; o > 0; o >>= 1) r = fmaxf(r, __shfl_down_sync(0xffffffff, r, o));
        if (lane == 0) sh[0] = r;
    }
    __syncthreads();
    r = sh[0];
    __syncthreads();
    return r;
}

// ---------------- embed: x = emb[ids]*sqrt(D) + pe ----------------
__global__ void te_embed_kernel(const int* __restrict__ ids,
                                const float* __restrict__ emb,
                                const float* __restrict__ pe) {
    int row = blockIdx.x;          // 0..2047  (b*S + s)
    int s = row & (SS - 1);
    int id = ids[row];
    const float* e = emb + (long long)id * DD;
    const float* p = pe + (long long)s * DD;
    float* x = g_x + (long long)row * DD;
    for (int j = threadIdx.x; j < DD; j += blockDim.x)
        x[j] = e[j] * 32.0f + p[j];   // sqrt(1024)=32
}

// ---------------- layernorm ----------------
__global__ void te_ln_kernel(const float* __restrict__ in,
                             float* __restrict__ out,
                             const float* __restrict__ gamma,
                             const float* __restrict__ beta) {
    int row = blockIdx.x;
    const float* x = in + (long long)row * DD;
    float s = 0.f, sq = 0.f;
    for (int j = threadIdx.x; j < DD; j += blockDim.x) {
        float v = x[j];
        s += v; sq += v * v;
    }
    s  = block_reduce_sum(s);
    sq = block_reduce_sum(sq);
    float mean = s * (1.0f / DD);
    float var  = sq * (1.0f / DD) - mean * mean;
    float inv  = rsqrtf(var + 1e-6f);
    float* o = out + (long long)row * DD;
    for (int j = threadIdx.x; j < DD; j += blockDim.x)
        o[j] = (x[j] - mean) * inv * gamma[j] + beta[j];
}

// ---------------- softmax over scores rows (with mask) ----------------
__global__ void te_softmax_kernel(const float* __restrict__ mask) {
    long long row = blockIdx.x;            // 0..B*H*S-1
    int b = (int)(row / (HH * SS));
    float* sc = g_scores + row * SS;
    const float* mrow = mask + (long long)b * SS;

    float mx = -3.4e38f;
    for (int k = threadIdx.x; k < SS; k += blockDim.x) {
        float v = sc[k];
        if (mrow[k] == 0.0f) { v = -1e9f; sc[k] = v; }
        mx = fmaxf(mx, v);
    }
    mx = block_reduce_max(mx);
    float sum = 0.f;
    for (int k = threadIdx.x; k < SS; k += blockDim.x) {
        float e = expf(sc[k] - mx);
        sc[k] = e;
        sum += e;
    }
    sum = block_reduce_sum(sum);
    float inv = 1.0f / sum;
    for (int k = threadIdx.x; k < SS; k += blockDim.x)
        sc[k] *= inv;
}

// ---------------- tf32 tensor-core GEMM ----------------
// C[z] = alpha * A[z] @ op(B[z]) (+bias) (relu) (+resid), per batch index z.
// op(B) = B   (TRANSB=false): B is K x N row-major (ldb = row stride)
// op(B) = B^T (TRANSB=true) : B is N x K row-major (ldb = row stride)
//
// Tile: 128x128x16, 256 threads = 8 warps in 2x4, each warp 64x32 via
// 4x4 grid of m16n8k8 tf32 mma. cp.async double-buffered smem.

#define BM 128
#define BN 128
#define BK 16
#define AP 20        // A smem row pitch (floats), conflict-free
#define BPN 132      // B smem (k-major) row pitch
#define BPT 20       // B smem (n-major, TRANSB) row pitch

__device__ __forceinline__ uint32_t f2tf32(float f) {
    uint32_t u;
    asm("cvt.rna.tf32.f32 %0, %1;" : "=r"(u) : "f"(f));
    return u;
}

__device__ __forceinline__ void mma_tf32(float c[4],
                                         uint32_t a0, uint32_t a1, uint32_t a2, uint32_t a3,
                                         uint32_t b0, uint32_t b1) {
    asm volatile(
        "mma.sync.aligned.m16n8k8.row.col.f32.tf32.tf32.f32 "
        "{%0,%1,%2,%3}, {%4,%5,%6,%7}, {%8,%9}, {%0,%1,%2,%3};"
        : "+f"(c[0]), "+f"(c[1]), "+f"(c[2]), "+f"(c[3])
        : "r"(a0), "r"(a1), "r"(a2), "r"(a3), "r"(b0), "r"(b1));
}

__device__ __forceinline__ void cp_async16(void* smem_dst, const void* gmem_src, bool pred) {
    uint32_t s = (uint32_t)__cvta_generic_to_shared(smem_dst);
    int sz = pred ? 16 : 0;
    asm volatile("cp.async.cg.shared.global [%0], [%1], 16, %2;\n"
                 :: "r"(s), "l"(gmem_src), "r"(sz));
}
__device__ __forceinline__ void cp_commit() { asm volatile("cp.async.commit_group;"); }
__device__ __forceinline__ void cp_wait0()  { asm volatile("cp.async.wait_group 0;"); }

template<bool TRANSB>
__global__ void __launch_bounds__(256)
te_mmgemm_kernel(int M, int N, int K,
                 const float* __restrict__ A, int lda, long long bsA,
                 const float* __restrict__ Bm, int ldb, long long bsB,
                 float* __restrict__ C, int ldc, long long bsC,
                 const float* __restrict__ bias,
                 const float* __restrict__ resid, int ldr, long long bsR,
                 float alpha, int relu) {
    A  += (long long)blockIdx.z * bsA;
    Bm += (long long)blockIdx.z * bsB;
    C  += (long long)blockIdx.z * bsC;
    if (resid) resid += (long long)blockIdx.z * bsR;

    __shared__ float As[2][BM][AP];
    __shared__ float Bs[2][TRANSB ? BN : BK][TRANSB ? BPT : BPN];

    const int t       = threadIdx.x;
    const int lane    = t & 31;
    const int wid     = t >> 5;
    const int warpRow = wid >> 2;   // 0..1
    const int warpCol = wid & 3;    // 0..3
    const int rowBase = blockIdx.y * BM;
    const int colBase = blockIdx.x * BN;

    float acc[4][4][4];
    #pragma unroll
    for (int i = 0; i < 4; i++)
        #pragma unroll
        for (int j = 0; j < 4; j++)
            #pragma unroll
            for (int e = 0; e < 4; e++) acc[i][j][e] = 0.f;

    const int numT = K / BK;

    // tile loaders --------------------------------------------------------
    auto load_tile = [&](int stage, int kt) {
        // A tile: 128 rows x 16 cols -> 512 16B chunks, 2 per thread
        #pragma unroll
        for (int it = 0; it < 2; it++) {
            int c   = t + it * 256;
            int r   = c >> 2;
            int c4  = c & 3;
            const float* src = A + (long long)(rowBase + r) * lda + kt + c4 * 4;
            cp_async16(&As[stage][r][c4 * 4], src, true);
        }
        if (TRANSB) {
            // B tile: rows = n (128), cols = k (16)
            #pragma unroll
            for (int it = 0; it < 2; it++) {
                int c  = t + it * 256;
                int nr = c >> 2;
                int k4 = c & 3;
                bool ok = (colBase + nr) < N;
                const float* src = Bm + (long long)(ok ? (colBase + nr) : 0) * ldb + kt + k4 * 4;
                cp_async16(&Bs[stage][nr][k4 * 4], src, ok);
            }
        } else {
            // B tile: rows = k (16), cols = n (128)
            #pragma unroll
            for (int it = 0; it < 2; it++) {
                int c  = t + it * 256;
                int kr = c >> 5;
                int n4 = c & 31;
                bool ok = (colBase + n4 * 4 + 3) < N;   // N is multiple of 4 always here
                const float* src = Bm + (long long)(kt + kr) * ldb + (ok ? (colBase + n4 * 4) : 0);
                cp_async16(&Bs[stage][kr][n4 * 4], src, ok);
            }
        }
        cp_commit();
    };

    load_tile(0, 0);

    const int r4 = lane >> 2;   // 0..7
    const int c4 = lane & 3;    // 0..3

    for (int ti = 0; ti < numT; ti++) {
        int cur = ti & 1;
        cp_wait0();
        __syncthreads();
        if (ti + 1 < numT) load_tile(cur ^ 1, (ti + 1) * BK);

        #pragma unroll
        for (int ks = 0; ks < 2; ks++) {
            int k0 = ks * 8;
            uint32_t af[4][4], bf[4][2];
            #pragma unroll
            for (int i = 0; i < 4; i++) {
                int mrow = warpRow * 64 + i * 16 + r4;
                af[i][0] = f2tf32(As[cur][mrow    ][k0 + c4    ]);
                af[i][1] = f2tf32(As[cur][mrow + 8][k0 + c4    ]);
                af[i][2] = f2tf32(As[cur][mrow    ][k0 + c4 + 4]);
                af[i][3] = f2tf32(As[cur][mrow + 8][k0 + c4 + 4]);
            }
            #pragma unroll
            for (int j = 0; j < 4; j++) {
                int ncol = warpCol * 32 + j * 8 + r4;
                int kb   = k0 + c4;
                if (TRANSB) {
                    bf[j][0] = f2tf32(Bs[cur][ncol][kb    ]);
                    bf[j][1] = f2tf32(Bs[cur][ncol][kb + 4]);
                } else {
                    bf[j][0] = f2tf32(Bs[cur][kb    ][ncol]);
                    bf[j][1] = f2tf32(Bs[cur][kb + 4][ncol]);
                }
            }
            #pragma unroll
            for (int i = 0; i < 4; i++)
                #pragma unroll
                for (int j = 0; j < 4; j++)
                    mma_tf32(acc[i][j], af[i][0], af[i][1], af[i][2], af[i][3],
                             bf[j][0], bf[j][1]);
        }
        __syncthreads();
    }

    // epilogue -------------------------------------------------------------
    #pragma unroll
    for (int i = 0; i < 4; i++) {
        int row0 = rowBase + warpRow * 64 + i * 16 + (lane >> 2);
        #pragma unroll
        for (int j = 0; j < 4; j++) {
            int col0 = colBase + warpCol * 32 + j * 8 + 2 * (lane & 3);
            #pragma unroll
            for (int half = 0; half < 2; half++) {
                int rr = row0 + half * 8;
                #pragma unroll
                for (int cc = 0; cc < 2; cc++) {
                    int gc = col0 + cc;
                    if (gc >= N) continue;
                    float v = acc[i][j][half * 2 + cc] * alpha;
                    if (bias)  v += bias[gc];
                    if (relu)  v = fmaxf(v, 0.f);
                    if (resid) v += resid[(long long)rr * ldr + gc];
                    C[(long long)rr * ldc + gc] = v;
                }
            }
        }
    }
}

// ---------------- host launch ----------------
extern "C" void kernel_launch(void* const* d_in, const int* in_sizes, int n_in,
                              void* d_out, int out_size) {
    const int*   ids    = (const int*)  d_in[0];
    const float* amask  = (const float*)d_in[1];
    const float* emb    = (const float*)d_in[2];
    const float* pe     = (const float*)d_in[3];
    const float* w_q    = (const float*)d_in[4];
    const float* w_k    = (const float*)d_in[5];
    const float* w_v    = (const float*)d_in[6];
    const float* w_o    = (const float*)d_in[7];
    const float* b_o    = (const float*)d_in[8];
    const float* w1     = (const float*)d_in[9];
    const float* b1     = (const float*)d_in[10];
    const float* w2     = (const float*)d_in[11];
    const float* b2     = (const float*)d_in[12];
    const float* ln1_s  = (const float*)d_in[13];
    const float* ln1_b  = (const float*)d_in[14];
    const float* ln2_s  = (const float*)d_in[15];
    const float* ln2_b  = (const float*)d_in[16];
    const float* lnf_s  = (const float*)d_in[17];
    const float* lnf_b  = (const float*)d_in[18];
    float* out = (float*)d_out;

    float *px, *ph, *pq, *pk, *pv, *patt, *psc, *pff;
    cudaGetSymbolAddress((void**)&px,  g_x);
    cudaGetSymbolAddress((void**)&ph,  g_h);
    cudaGetSymbolAddress((void**)&pq,  g_q);
    cudaGetSymbolAddress((void**)&pk,  g_k);
    cudaGetSymbolAddress((void**)&pv,  g_v);
    cudaGetSymbolAddress((void**)&patt,g_att);
    cudaGetSymbolAddress((void**)&psc, g_scores);
    cudaGetSymbolAddress((void**)&pff, g_ff);

    te_embed_kernel<<<ROWS, 256>>>(ids, emb, pe);

    for (int l = 0; l < LL; l++) {
        const float* wq  = w_q + (long long)l * DD * DD;
        const float* wk  = w_k + (long long)l * DD * DD;
        const float* wv  = w_v + (long long)l * DD * DD;
        const float* wo  = w_o + (long long)l * DD * DD;
        const float* bo  = b_o + (long long)l * DD;
        const float* W1  = w1  + (long long)l * DD * FF;
        const float* B1  = b1  + (long long)l * FF;
        const float* W2  = w2  + (long long)l * FF * DD;
        const float* B2  = b2  + (long long)l * DD;

        // LN1
        te_ln_kernel<<<ROWS, 256>>>(px, ph, ln1_s + (long long)l*DD, ln1_b + (long long)l*DD);

        // Q, K, V projections: (2048,1024) @ (1024,1024)
        dim3 gProj(DD / BN, ROWS / BM, 1);
        te_mmgemm_kernel<false><<<gProj, 256>>>(ROWS, DD, DD, ph, DD, 0, wq, DD, 0,
                                                pq, DD, 0, nullptr, nullptr, 0, 0, 1.f, 0);
        te_mmgemm_kernel<false><<<gProj, 256>>>(ROWS, DD, DD, ph, DD, 0, wk, DD, 0,
                                                pk, DD, 0, nullptr, nullptr, 0, 0, 1.f, 0);
        te_mmgemm_kernel<false><<<gProj, 256>>>(ROWS, DD, DD, ph, DD, 0, wv, DD, 0,
                                                pv, DD, 0, nullptr, nullptr, 0, 0, 1.f, 0);

        // scores[b,h] = q_bh @ k_bh^T / 8 ;  per b, batch over heads (z)
        for (int b = 0; b < BB; b++) {
            dim3 gSc(SS / BN, SS / BM, HH);
            te_mmgemm_kernel<true><<<gSc, 256>>>(SS, SS, DKK,
                pq + (long long)b * SS * DD, DD, DKK,
                pk + (long long)b * SS * DD, DD, DKK,
                psc + (long long)b * HH * SS * SS, SS, (long long)SS * SS,
                nullptr, nullptr, 0, 0, 0.125f, 0);
        }

        te_softmax_kernel<<<BB * HH * SS, 256>>>(amask);

        // attn @ v : per b, batch over heads
        for (int b = 0; b < BB; b++) {
            dim3 gAv(1, SS / BM, HH);
            te_mmgemm_kernel<false><<<gAv, 256>>>(SS, DKK, SS,
                psc + (long long)b * HH * SS * SS, SS, (long long)SS * SS,
                pv + (long long)b * SS * DD, DD, DKK,
                patt + (long long)b * SS * DD, DD, DKK,
                nullptr, nullptr, 0, 0, 1.f, 0);
        }

        // Wo projection + bias + residual -> x
        te_mmgemm_kernel<false><<<gProj, 256>>>(ROWS, DD, DD, patt, DD, 0, wo, DD, 0,
                                                px, DD, 0, bo, px, DD, 0, 1.f, 0);

        // LN2
        te_ln_kernel<<<ROWS, 256>>>(px, ph, ln2_s + (long long)l*DD, ln2_b + (long long)l*DD);

        // FF1: relu(h @ W1 + B1)
        dim3 gF1(FF / BN, ROWS / BM, 1);
        te_mmgemm_kernel<false><<<gF1, 256>>>(ROWS, FF, DD, ph, DD, 0, W1, FF, 0,
                                              pff, FF, 0, B1, nullptr, 0, 0, 1.f, 1);
        // FF2: ff @ W2 + B2 + residual -> x
        dim3 gF2(DD / BN, ROWS / BM, 1);
        te_mmgemm_kernel<false><<<gF2, 256>>>(ROWS, DD, FF, pff, FF, 0, W2, DD, 0,
                                              px, DD, 0, B2, px, DD, 0, 1.f, 0);
    }

    // final LN -> out
    te_ln_kernel<<<ROWS, 256>>>(px, out, lnf_s, lnf_b);
}

// round 3
// speedup vs baseline: 3.4357x; 1.0002x over previous
#include <cuda_runtime.h>
#include <math.h>
#include <stdint.h>

// Problem dims (fixed by the reference)
#define BB 2
#define SS 1024
#define DD 1024
#define HH 16
#define DKK 64
#define FF 4096
#define LL 6
#define ROWS (BB*SS)   // 2048

// ---------------- scratch (static device globals; no allocs allowed) -------
__device__ float g_x  [ROWS*DD];            // residual stream
__device__ float g_h  [ROWS*DD];            // LN output
__device__ float g_q  [ROWS*DD];
__device__ float g_k  [ROWS*DD];
__device__ float g_v  [ROWS*DD];
__device__ float g_att[ROWS*DD];            // attention output pre-Wo
__device__ float g_scores[(long long)BB*HH*SS*SS]; // 128 MB
__device__ float g_ff [ROWS*FF];            // 32 MB

// ---------------- reductions ----------------
__device__ __forceinline__ float block_reduce_sum(float v) {
    __shared__ float sh[32];
    int lane = threadIdx.x & 31, wid = threadIdx.x >> 5;
    #pragma unroll
    for (int o = 16; o > 0; o >>= 1) v += __shfl_down_sync(0xffffffff, v, o);
    if (lane == 0) sh[wid] = v;
    __syncthreads();
    float r = 0.f;
    if (wid == 0) {
        r = (lane < (blockDim.x >> 5)) ? sh[lane] : 0.f;
        #pragma unroll
        for (int o = 16; o > 0; o >>= 1) r += __shfl_down_sync(0xffffffff, r, o);
        if (lane == 0) sh[0] = r;
    }
    __syncthreads();
    r = sh[0];
    __syncthreads();
    return r;
}

__device__ __forceinline__ float block_reduce_max(float v) {
    __shared__ float sh[32];
    int lane = threadIdx.x & 31, wid = threadIdx.x >> 5;
    #pragma unroll
    for (int o = 16; o > 0; o >>= 1) v = fmaxf(v, __shfl_down_sync(0xffffffff, v, o));
    if (lane == 0) sh[wid] = v;
    __syncthreads();
    float r = -3.4e38f;
    if (wid == 0) {
        r = (lane < (blockDim.x >> 5)) ? sh[lane] : -3.4e38f;
        #pragma unroll
        for (int o = 16; o > 0; o >>= 1) r = fmaxf(r, __shfl_down_sync(0xffffffff, r, o));
        if (lane == 0) sh[0] = r;
    }
    __syncthreads();
    r = sh[0];
    __syncthreads();
    return r;
}

// ---------------- embed: x = emb[ids]*sqrt(D) + pe ----------------
__global__ void te_embed_kernel(const int* __restrict__ ids,
                                const float* __restrict__ emb,
                                const float* __restrict__ pe) {
    int row = blockIdx.x;          // 0..2047  (b*S + s)
    int s = row & (SS - 1);
    int id = ids[row];
    const float* e = emb + (long long)id * DD;
    const float* p = pe + (long long)s * DD;
    float* x = g_x + (long long)row * DD;
    for (int j = threadIdx.x; j < DD; j += blockDim.x)
        x[j] = e[j] * 32.0f + p[j];   // sqrt(1024)=32
}

// ---------------- layernorm ----------------
__global__ void te_ln_kernel(const float* __restrict__ in,
                             float* __restrict__ out,
                             const float* __restrict__ gamma,
                             const float* __restrict__ beta) {
    int row = blockIdx.x;
    const float* x = in + (long long)row * DD;
    float s = 0.f, sq = 0.f;
    for (int j = threadIdx.x; j < DD; j += blockDim.x) {
        float v = x[j];
        s += v; sq += v * v;
    }
    s  = block_reduce_sum(s);
    sq = block_reduce_sum(sq);
    float mean = s * (1.0f / DD);
    float var  = sq * (1.0f / DD) - mean * mean;
    float inv  = rsqrtf(var + 1e-6f);
    float* o = out + (long long)row * DD;
    for (int j = threadIdx.x; j < DD; j += blockDim.x)
        o[j] = (x[j] - mean) * inv * gamma[j] + beta[j];
}

// ---------------- softmax over scores rows (with mask) ----------------
__global__ void te_softmax_kernel(const float* __restrict__ mask) {
    long long row = blockIdx.x;            // 0..B*H*S-1
    int b = (int)(row / (HH * SS));
    float* sc = g_scores + row * SS;
    const float* mrow = mask + (long long)b * SS;

    float mx = -3.4e38f;
    for (int k = threadIdx.x; k < SS; k += blockDim.x) {
        float v = sc[k];
        if (mrow[k] == 0.0f) { v = -1e9f; sc[k] = v; }
        mx = fmaxf(mx, v);
    }
    mx = block_reduce_max(mx);
    float sum = 0.f;
    for (int k = threadIdx.x; k < SS; k += blockDim.x) {
        float e = expf(sc[k] - mx);
        sc[k] = e;
        sum += e;
    }
    sum = block_reduce_sum(sum);
    float inv = 1.0f / sum;
    for (int k = threadIdx.x; k < SS; k += blockDim.x)
        sc[k] *= inv;
}

// ---------------- tf32 tensor-core GEMM ----------------
// C[z] = alpha * A[z] @ op(B[z]) (+bias) (relu) (+resid), per batch index z.
// op(B) = B   (TRANSB=false): B is K x N row-major (ldb = row stride)
// op(B) = B^T (TRANSB=true) : B is N x K row-major (ldb = row stride)
//
// Tile: 128x128x16, 256 threads = 8 warps in 2x4, each warp 64x32 via
// 4x4 grid of m16n8k8 tf32 mma. cp.async double-buffered smem.

#define BM 128
#define BN 128
#define BK 16
#define AP 20        // A smem row pitch (floats), conflict-free
#define BPN 132      // B smem (k-major) row pitch
#define BPT 20       // B smem (n-major, TRANSB) row pitch

__device__ __forceinline__ uint32_t f2tf32(float f) {
    uint32_t u;
    asm("cvt.rna.tf32.f32 %0, %1;" : "=r"(u) : "f"(f));
    return u;
}

__device__ __forceinline__ void mma_tf32(float c[4],
                                         uint32_t a0, uint32_t a1, uint32_t a2, uint32_t a3,
                                         uint32_t b0, uint32_t b1) {
    asm volatile(
        "mma.sync.aligned.m16n8k8.row.col.f32.tf32.tf32.f32 "
        "{%0,%1,%2,%3}, {%4,%5,%6,%7}, {%8,%9}, {%0,%1,%2,%3};"
        : "+f"(c[0]), "+f"(c[1]), "+f"(c[2]), "+f"(c[3])
        : "r"(a0), "r"(a1), "r"(a2), "r"(a3), "r"(b0), "r"(b1));
}

__device__ __forceinline__ void cp_async16(void* smem_dst, const void* gmem_src, bool pred) {
    uint32_t s = (uint32_t)__cvta_generic_to_shared(smem_dst);
    int sz = pred ? 16 : 0;
    asm volatile("cp.async.cg.shared.global [%0], [%1], 16, %2;\n"
                 :: "r"(s), "l"(gmem_src), "r"(sz));
}
__device__ __forceinline__ void cp_commit() { asm volatile("cp.async.commit_group;"); }
__device__ __forceinline__ void cp_wait0()  { asm volatile("cp.async.wait_group 0;"); }

template<bool TRANSB>
__global__ void __launch_bounds__(256)
te_mmgemm_kernel(int M, int N, int K,
                 const float* __restrict__ A, int lda, long long bsA,
                 const float* __restrict__ Bm, int ldb, long long bsB,
                 float* __restrict__ C, int ldc, long long bsC,
                 const float* __restrict__ bias,
                 const float* __restrict__ resid, int ldr, long long bsR,
                 float alpha, int relu) {
    A  += (long long)blockIdx.z * bsA;
    Bm += (long long)blockIdx.z * bsB;
    C  += (long long)blockIdx.z * bsC;
    if (resid) resid += (long long)blockIdx.z * bsR;

    __shared__ float As[2][BM][AP];
    __shared__ float Bs[2][TRANSB ? BN : BK][TRANSB ? BPT : BPN];

    const int t       = threadIdx.x;
    const int lane    = t & 31;
    const int wid     = t >> 5;
    const int warpRow = wid >> 2;   // 0..1
    const int warpCol = wid & 3;    // 0..3
    const int rowBase = blockIdx.y * BM;
    const int colBase = blockIdx.x * BN;

    float acc[4][4][4];
    #pragma unroll
    for (int i = 0; i < 4; i++)
        #pragma unroll
        for (int j = 0; j < 4; j++)
            #pragma unroll
            for (int e = 0; e < 4; e++) acc[i][j][e] = 0.f;

    const int numT = K / BK;

    // tile loaders --------------------------------------------------------
    auto load_tile = [&](int stage, int kt) {
        // A tile: 128 rows x 16 cols -> 512 16B chunks, 2 per thread
        #pragma unroll
        for (int it = 0; it < 2; it++) {
            int c   = t + it * 256;
            int r   = c >> 2;
            int c4  = c & 3;
            const float* src = A + (long long)(rowBase + r) * lda + kt + c4 * 4;
            cp_async16(&As[stage][r][c4 * 4], src, true);
        }
        if (TRANSB) {
            // B tile: rows = n (128), cols = k (16)
            #pragma unroll
            for (int it = 0; it < 2; it++) {
                int c  = t + it * 256;
                int nr = c >> 2;
                int k4 = c & 3;
                bool ok = (colBase + nr) < N;
                const float* src = Bm + (long long)(ok ? (colBase + nr) : 0) * ldb + kt + k4 * 4;
                cp_async16(&Bs[stage][nr][k4 * 4], src, ok);
            }
        } else {
            // B tile: rows = k (16), cols = n (128)
            #pragma unroll
            for (int it = 0; it < 2; it++) {
                int c  = t + it * 256;
                int kr = c >> 5;
                int n4 = c & 31;
                bool ok = (colBase + n4 * 4 + 3) < N;   // N is multiple of 4 always here
                const float* src = Bm + (long long)(kt + kr) * ldb + (ok ? (colBase + n4 * 4) : 0);
                cp_async16(&Bs[stage][kr][n4 * 4], src, ok);
            }
        }
        cp_commit();
    };

    load_tile(0, 0);

    const int r4 = lane >> 2;   // 0..7
    const int c4 = lane & 3;    // 0..3

    for (int ti = 0; ti < numT; ti++) {
        int cur = ti & 1;
        cp_wait0();
        __syncthreads();
        if (ti + 1 < numT) load_tile(cur ^ 1, (ti + 1) * BK);

        #pragma unroll
        for (int ks = 0; ks < 2; ks++) {
            int k0 = ks * 8;
            uint32_t af[4][4], bf[4][2];
            #pragma unroll
            for (int i = 0; i < 4; i++) {
                int mrow = warpRow * 64 + i * 16 + r4;
                af[i][0] = f2tf32(As[cur][mrow    ][k0 + c4    ]);
                af[i][1] = f2tf32(As[cur][mrow + 8][k0 + c4    ]);
                af[i][2] = f2tf32(As[cur][mrow    ][k0 + c4 + 4]);
                af[i][3] = f2tf32(As[cur][mrow + 8][k0 + c4 + 4]);
            }
            #pragma unroll
            for (int j = 0; j < 4; j++) {
                int ncol = warpCol * 32 + j * 8 + r4;
                int kb   = k0 + c4;
                if (TRANSB) {
                    bf[j][0] = f2tf32(Bs[cur][ncol][kb    ]);
                    bf[j][1] = f2tf32(Bs[cur][ncol][kb + 4]);
                } else {
                    bf[j][0] = f2tf32(Bs[cur][kb    ][ncol]);
                    bf[j][1] = f2tf32(Bs[cur][kb + 4][ncol]);
                }
            }
            #pragma unroll
            for (int i = 0; i < 4; i++)
                #pragma unroll
                for (int j = 0; j < 4; j++)
                    mma_tf32(acc[i][j], af[i][0], af[i][1], af[i][2], af[i][3],
                             bf[j][0], bf[j][1]);
        }
        __syncthreads();
    }

    // epilogue -------------------------------------------------------------
    #pragma unroll
    for (int i = 0; i < 4; i++) {
        int row0 = rowBase + warpRow * 64 + i * 16 + (lane >> 2);
        #pragma unroll
        for (int j = 0; j < 4; j++) {
            int col0 = colBase + warpCol * 32 + j * 8 + 2 * (lane & 3);
            #pragma unroll
            for (int half = 0; half < 2; half++) {
                int rr = row0 + half * 8;
                #pragma unroll
                for (int cc = 0; cc < 2; cc++) {
                    int gc = col0 + cc;
                    if (gc >= N) continue;
                    float v = acc[i][j][half * 2 + cc] * alpha;
                    if (bias)  v += bias[gc];
                    if (relu)  v = fmaxf(v, 0.f);
                    if (resid) v += resid[(long long)rr * ldr + gc];
                    C[(long long)rr * ldc + gc] = v;
                }
            }
        }
    }
}

// ---------------- host launch ----------------
extern "C" void kernel_launch(void* const* d_in, const int* in_sizes, int n_in,
                              void* d_out, int out_size) {
    const int*   ids    = (const int*)  d_in[0];
    const float* amask  = (const float*)d_in[1];
    const float* emb    = (const float*)d_in[2];
    const float* pe     = (const float*)d_in[3];
    const float* w_q    = (const float*)d_in[4];
    const float* w_k    = (const float*)d_in[5];
    const float* w_v    = (const float*)d_in[6];
    const float* w_o    = (const float*)d_in[7];
    const float* b_o    = (const float*)d_in[8];
    const float* w1     = (const float*)d_in[9];
    const float* b1     = (const float*)d_in[10];
    const float* w2     = (const float*)d_in[11];
    const float* b2     = (const float*)d_in[12];
    const float* ln1_s  = (const float*)d_in[13];
    const float* ln1_b  = (const float*)d_in[14];
    const float* ln2_s  = (const float*)d_in[15];
    const float* ln2_b  = (const float*)d_in[16];
    const float* lnf_s  = (const float*)d_in[17];
    const float* lnf_b  = (const float*)d_in[18];
    float* out = (float*)d_out;

    float *px, *ph, *pq, *pk, *pv, *patt, *psc, *pff;
    cudaGetSymbolAddress((void**)&px,  g_x);
    cudaGetSymbolAddress((void**)&ph,  g_h);
    cudaGetSymbolAddress((void**)&pq,  g_q);
    cudaGetSymbolAddress((void**)&pk,  g_k);
    cudaGetSymbolAddress((void**)&pv,  g_v);
    cudaGetSymbolAddress((void**)&patt,g_att);
    cudaGetSymbolAddress((void**)&psc, g_scores);
    cudaGetSymbolAddress((void**)&pff, g_ff);

    te_embed_kernel<<<ROWS, 256>>>(ids, emb, pe);

    for (int l = 0; l < LL; l++) {
        const float* wq  = w_q + (long long)l * DD * DD;
        const float* wk  = w_k + (long long)l * DD * DD;
        const float* wv  = w_v + (long long)l * DD * DD;
        const float* wo  = w_o + (long long)l * DD * DD;
        const float* bo  = b_o + (long long)l * DD;
        const float* W1  = w1  + (long long)l * DD * FF;
        const float* B1  = b1  + (long long)l * FF;
        const float* W2  = w2  + (long long)l * FF * DD;
        const float* B2  = b2  + (long long)l * DD;

        // LN1
        te_ln_kernel<<<ROWS, 256>>>(px, ph, ln1_s + (long long)l*DD, ln1_b + (long long)l*DD);

        // Q, K, V projections: (2048,1024) @ (1024,1024)
        dim3 gProj(DD / BN, ROWS / BM, 1);
        te_mmgemm_kernel<false><<<gProj, 256>>>(ROWS, DD, DD, ph, DD, 0, wq, DD, 0,
                                                pq, DD, 0, nullptr, nullptr, 0, 0, 1.f, 0);
        te_mmgemm_kernel<false><<<gProj, 256>>>(ROWS, DD, DD, ph, DD, 0, wk, DD, 0,
                                                pk, DD, 0, nullptr, nullptr, 0, 0, 1.f, 0);
        te_mmgemm_kernel<false><<<gProj, 256>>>(ROWS, DD, DD, ph, DD, 0, wv, DD, 0,
                                                pv, DD, 0, nullptr, nullptr, 0, 0, 1.f, 0);

        // scores[b,h] = q_bh @ k_bh^T / 8 ;  per b, batch over heads (z)
        for (int b = 0; b < BB; b++) {
            dim3 gSc(SS / BN, SS / BM, HH);
            te_mmgemm_kernel<true><<<gSc, 256>>>(SS, SS, DKK,
                pq + (long long)b * SS * DD, DD, DKK,
                pk + (long long)b * SS * DD, DD, DKK,
                psc + (long long)b * HH * SS * SS, SS, (long long)SS * SS,
                nullptr, nullptr, 0, 0, 0.125f, 0);
        }

        te_softmax_kernel<<<BB * HH * SS, 256>>>(amask);

        // attn @ v : per b, batch over heads
        for (int b = 0; b < BB; b++) {
            dim3 gAv(1, SS / BM, HH);
            te_mmgemm_kernel<false><<<gAv, 256>>>(SS, DKK, SS,
                psc + (long long)b * HH * SS * SS, SS, (long long)SS * SS,
                pv + (long long)b * SS * DD, DD, DKK,
                patt + (long long)b * SS * DD, DD, DKK,
                nullptr, nullptr, 0, 0, 1.f, 0);
        }

        // Wo projection + bias + residual -> x
        te_mmgemm_kernel<false><<<gProj, 256>>>(ROWS, DD, DD, patt, DD, 0, wo, DD, 0,
                                                px, DD, 0, bo, px, DD, 0, 1.f, 0);

        // LN2
        te_ln_kernel<<<ROWS, 256>>>(px, ph, ln2_s + (long long)l*DD, ln2_b + (long long)l*DD);

        // FF1: relu(h @ W1 + B1)
        dim3 gF1(FF / BN, ROWS / BM, 1);
        te_mmgemm_kernel<false><<<gF1, 256>>>(ROWS, FF, DD, ph, DD, 0, W1, FF, 0,
                                              pff, FF, 0, B1, nullptr, 0, 0, 1.f, 1);
        // FF2: ff @ W2 + B2 + residual -> x
        dim3 gF2(DD / BN, ROWS / BM, 1);
        te_mmgemm_kernel<false><<<gF2, 256>>>(ROWS, DD, FF, pff, FF, 0, W2, DD, 0,
                                              px, DD, 0, B2, px, DD, 0, 1.f, 0);
    }

    // final LN -> out
    te_ln_kernel<<<ROWS, 256>>>(px, out, lnf_s, lnf_b);
}

// round 4
// speedup vs baseline: 3.4385x; 1.0008x over previous
#include <cuda_runtime.h>
#include <math.h>
#include <stdint.h>

// Problem dims (fixed by the reference)
#define BB 2
#define SS 1024
#define DD 1024
#define HH 16
#define DKK 64
#define FF 4096
#define LL 6
#define ROWS (BB*SS)   // 2048

// ---------------- scratch (static device globals; no allocs allowed) -------
__device__ float g_x  [ROWS*DD];            // residual stream
__device__ float g_h  [ROWS*DD];            // LN output
__device__ float g_q  [ROWS*DD];
__device__ float g_k  [ROWS*DD];
__device__ float g_v  [ROWS*DD];
__device__ float g_att[ROWS*DD];            // attention output pre-Wo
__device__ float g_scores[(long long)BB*HH*SS*SS]; // 128 MB
__device__ float g_ff [ROWS*FF];            // 32 MB

// ---------------- reductions ----------------
__device__ __forceinline__ float block_reduce_sum(float v) {
    __shared__ float sh[32];
    int lane = threadIdx.x & 31, wid = threadIdx.x >> 5;
    #pragma unroll
    for (int o = 16; o > 0; o >>= 1) v += __shfl_down_sync(0xffffffff, v, o);
    if (lane == 0) sh[wid] = v;
    __syncthreads();
    float r = 0.f;
    if (wid == 0) {
        r = (lane < (blockDim.x >> 5)) ? sh[lane] : 0.f;
        #pragma unroll
        for (int o = 16; o > 0; o >>= 1) r += __shfl_down_sync(0xffffffff, r, o);
        if (lane == 0) sh[0] = r;
    }
    __syncthreads();
    r = sh[0];
    __syncthreads();
    return r;
}

__device__ __forceinline__ float block_reduce_max(float v) {
    __shared__ float sh[32];
    int lane = threadIdx.x & 31, wid = threadIdx.x >> 5;
    #pragma unroll
    for (int o = 16; o > 0; o >>= 1) v = fmaxf(v, __shfl_down_sync(0xffffffff, v, o));
    if (lane == 0) sh[wid] = v;
    __syncthreads();
    float r = -3.4e38f;
    if (wid == 0) {
        r = (lane < (blockDim.x >> 5)) ? sh[lane] : -3.4e38f;
        #pragma unroll
        for (int o = 16; o > 0; o >>= 1) r = fmaxf(r, __shfl_down_sync(0xffffffff, r, o));
        if (lane == 0) sh[0] = r;
    }
    __syncthreads();
    r = sh[0];
    __syncthreads();
    return r;
}

// ---------------- embed: x = emb[ids]*sqrt(D) + pe ----------------
__global__ void te_embed_kernel(const int* __restrict__ ids,
                                const float* __restrict__ emb,
                                const float* __restrict__ pe) {
    int row = blockIdx.x;          // 0..2047  (b*S + s)
    int s = row & (SS - 1);
    int id = ids[row];
    const float* e = emb + (long long)id * DD;
    const float* p = pe + (long long)s * DD;
    float* x = g_x + (long long)row * DD;
    for (int j = threadIdx.x; j < DD; j += blockDim.x)
        x[j] = e[j] * 32.0f + p[j];   // sqrt(1024)=32
}

// ---------------- layernorm ----------------
__global__ void te_ln_kernel(const float* __restrict__ in,
                             float* __restrict__ out,
                             const float* __restrict__ gamma,
                             const float* __restrict__ beta) {
    int row = blockIdx.x;
    const float* x = in + (long long)row * DD;
    float s = 0.f, sq = 0.f;
    for (int j = threadIdx.x; j < DD; j += blockDim.x) {
        float v = x[j];
        s += v; sq += v * v;
    }
    s  = block_reduce_sum(s);
    sq = block_reduce_sum(sq);
    float mean = s * (1.0f / DD);
    float var  = sq * (1.0f / DD) - mean * mean;
    float inv  = rsqrtf(var + 1e-6f);
    float* o = out + (long long)row * DD;
    for (int j = threadIdx.x; j < DD; j += blockDim.x)
        o[j] = (x[j] - mean) * inv * gamma[j] + beta[j];
}

// ---------------- softmax over scores rows (with mask) ----------------
__global__ void te_softmax_kernel(const float* __restrict__ mask) {
    long long row = blockIdx.x;            // 0..B*H*S-1
    int b = (int)(row / (HH * SS));
    float* sc = g_scores + row * SS;
    const float* mrow = mask + (long long)b * SS;

    float mx = -3.4e38f;
    for (int k = threadIdx.x; k < SS; k += blockDim.x) {
        float v = sc[k];
        if (mrow[k] == 0.0f) { v = -1e9f; sc[k] = v; }
        mx = fmaxf(mx, v);
    }
    mx = block_reduce_max(mx);
    float sum = 0.f;
    for (int k = threadIdx.x; k < SS; k += blockDim.x) {
        float e = expf(sc[k] - mx);
        sc[k] = e;
        sum += e;
    }
    sum = block_reduce_sum(sum);
    float inv = 1.0f / sum;
    for (int k = threadIdx.x; k < SS; k += blockDim.x)
        sc[k] *= inv;
}

// ---------------- tf32 tensor-core GEMM ----------------
// C[z] = alpha * A[z] @ op(B[z]) (+bias) (relu) (+resid), per batch index z.
// op(B) = B   (TRANSB=false): B is K x N row-major (ldb = row stride)
// op(B) = B^T (TRANSB=true) : B is N x K row-major (ldb = row stride)
//
// Tile: 128x128x16, 256 threads = 8 warps in 2x4, each warp 64x32 via
// 4x4 grid of m16n8k8 tf32 mma. cp.async double-buffered smem.

#define BM 128
#define BN 128
#define BK 16
#define AP 20        // A smem row pitch (floats), conflict-free
#define BPN 132      // B smem (k-major) row pitch
#define BPT 20       // B smem (n-major, TRANSB) row pitch

__device__ __forceinline__ uint32_t f2tf32(float f) {
    uint32_t u;
    asm("cvt.rna.tf32.f32 %0, %1;" : "=r"(u) : "f"(f));
    return u;
}

__device__ __forceinline__ void mma_tf32(float c[4],
                                         uint32_t a0, uint32_t a1, uint32_t a2, uint32_t a3,
                                         uint32_t b0, uint32_t b1) {
    asm volatile(
        "mma.sync.aligned.m16n8k8.row.col.f32.tf32.tf32.f32 "
        "{%0,%1,%2,%3}, {%4,%5,%6,%7}, {%8,%9}, {%0,%1,%2,%3};"
        : "+f"(c[0]), "+f"(c[1]), "+f"(c[2]), "+f"(c[3])
        : "r"(a0), "r"(a1), "r"(a2), "r"(a3), "r"(b0), "r"(b1));
}

__device__ __forceinline__ void cp_async16(void* smem_dst, const void* gmem_src, bool pred) {
    uint32_t s = (uint32_t)__cvta_generic_to_shared(smem_dst);
    int sz = pred ? 16 : 0;
    asm volatile("cp.async.cg.shared.global [%0], [%1], 16, %2;\n"
                 :: "r"(s), "l"(gmem_src), "r"(sz));
}
__device__ __forceinline__ void cp_commit() { asm volatile("cp.async.commit_group;"); }
__device__ __forceinline__ void cp_wait0()  { asm volatile("cp.async.wait_group 0;"); }

template<bool TRANSB>
__global__ void __launch_bounds__(256)
te_mmgemm_kernel(int M, int N, int K,
                 const float* __restrict__ A, int lda, long long bsA,
                 const float* __restrict__ Bm, int ldb, long long bsB,
                 float* __restrict__ C, int ldc, long long bsC,
                 const float* __restrict__ bias,
                 const float* __restrict__ resid, int ldr, long long bsR,
                 float alpha, int relu) {
    A  += (long long)blockIdx.z * bsA;
    Bm += (long long)blockIdx.z * bsB;
    C  += (long long)blockIdx.z * bsC;
    if (resid) resid += (long long)blockIdx.z * bsR;

    __shared__ float As[2][BM][AP];
    __shared__ float Bs[2][TRANSB ? BN : BK][TRANSB ? BPT : BPN];

    const int t       = threadIdx.x;
    const int lane    = t & 31;
    const int wid     = t >> 5;
    const int warpRow = wid >> 2;   // 0..1
    const int warpCol = wid & 3;    // 0..3
    const int rowBase = blockIdx.y * BM;
    const int colBase = blockIdx.x * BN;

    float acc[4][4][4];
    #pragma unroll
    for (int i = 0; i < 4; i++)
        #pragma unroll
        for (int j = 0; j < 4; j++)
            #pragma unroll
            for (int e = 0; e < 4; e++) acc[i][j][e] = 0.f;

    const int numT = K / BK;

    // tile loaders --------------------------------------------------------
    auto load_tile = [&](int stage, int kt) {
        // A tile: 128 rows x 16 cols -> 512 16B chunks, 2 per thread
        #pragma unroll
        for (int it = 0; it < 2; it++) {
            int c   = t + it * 256;
            int r   = c >> 2;
            int c4  = c & 3;
            const float* src = A + (long long)(rowBase + r) * lda + kt + c4 * 4;
            cp_async16(&As[stage][r][c4 * 4], src, true);
        }
        if (TRANSB) {
            // B tile: rows = n (128), cols = k (16)
            #pragma unroll
            for (int it = 0; it < 2; it++) {
                int c  = t + it * 256;
                int nr = c >> 2;
                int k4 = c & 3;
                bool ok = (colBase + nr) < N;
                const float* src = Bm + (long long)(ok ? (colBase + nr) : 0) * ldb + kt + k4 * 4;
                cp_async16(&Bs[stage][nr][k4 * 4], src, ok);
            }
        } else {
            // B tile: rows = k (16), cols = n (128)
            #pragma unroll
            for (int it = 0; it < 2; it++) {
                int c  = t + it * 256;
                int kr = c >> 5;
                int n4 = c & 31;
                bool ok = (colBase + n4 * 4 + 3) < N;   // N is multiple of 4 always here
                const float* src = Bm + (long long)(kt + kr) * ldb + (ok ? (colBase + n4 * 4) : 0);
                cp_async16(&Bs[stage][kr][n4 * 4], src, ok);
            }
        }
        cp_commit();
    };

    load_tile(0, 0);

    const int r4 = lane >> 2;   // 0..7
    const int c4 = lane & 3;    // 0..3

    for (int ti = 0; ti < numT; ti++) {
        int cur = ti & 1;
        cp_wait0();
        __syncthreads();
        if (ti + 1 < numT) load_tile(cur ^ 1, (ti + 1) * BK);

        #pragma unroll
        for (int ks = 0; ks < 2; ks++) {
            int k0 = ks * 8;
            uint32_t af[4][4], bf[4][2];
            #pragma unroll
            for (int i = 0; i < 4; i++) {
                int mrow = warpRow * 64 + i * 16 + r4;
                af[i][0] = f2tf32(As[cur][mrow    ][k0 + c4    ]);
                af[i][1] = f2tf32(As[cur][mrow + 8][k0 + c4    ]);
                af[i][2] = f2tf32(As[cur][mrow    ][k0 + c4 + 4]);
                af[i][3] = f2tf32(As[cur][mrow + 8][k0 + c4 + 4]);
            }
            #pragma unroll
            for (int j = 0; j < 4; j++) {
                int ncol = warpCol * 32 + j * 8 + r4;
                int kb   = k0 + c4;
                if (TRANSB) {
                    bf[j][0] = f2tf32(Bs[cur][ncol][kb    ]);
                    bf[j][1] = f2tf32(Bs[cur][ncol][kb + 4]);
                } else {
                    bf[j][0] = f2tf32(Bs[cur][kb    ][ncol]);
                    bf[j][1] = f2tf32(Bs[cur][kb + 4][ncol]);
                }
            }
            #pragma unroll
            for (int i = 0; i < 4; i++)
                #pragma unroll
                for (int j = 0; j < 4; j++)
                    mma_tf32(acc[i][j], af[i][0], af[i][1], af[i][2], af[i][3],
                             bf[j][0], bf[j][1]);
        }
        __syncthreads();
    }

    // epilogue -------------------------------------------------------------
    #pragma unroll
    for (int i = 0; i < 4; i++) {
        int row0 = rowBase + warpRow * 64 + i * 16 + (lane >> 2);
        #pragma unroll
        for (int j = 0; j < 4; j++) {
            int col0 = colBase + warpCol * 32 + j * 8 + 2 * (lane & 3);
            #pragma unroll
            for (int half = 0; half < 2; half++) {
                int rr = row0 + half * 8;
                #pragma unroll
                for (int cc = 0; cc < 2; cc++) {
                    int gc = col0 + cc;
                    if (gc >= N) continue;
                    float v = acc[i][j][half * 2 + cc] * alpha;
                    if (bias)  v += bias[gc];
                    if (relu)  v = fmaxf(v, 0.f);
                    if (resid) v += resid[(long long)rr * ldr + gc];
                    C[(long long)rr * ldc + gc] = v;
                }
            }
        }
    }
}

// ---------------- host launch ----------------
extern "C" void kernel_launch(void* const* d_in, const int* in_sizes, int n_in,
                              void* d_out, int out_size) {
    const int*   ids    = (const int*)  d_in[0];
    const float* amask  = (const float*)d_in[1];
    const float* emb    = (const float*)d_in[2];
    const float* pe     = (const float*)d_in[3];
    const float* w_q    = (const float*)d_in[4];
    const float* w_k    = (const float*)d_in[5];
    const float* w_v    = (const float*)d_in[6];
    const float* w_o    = (const float*)d_in[7];
    const float* b_o    = (const float*)d_in[8];
    const float* w1     = (const float*)d_in[9];
    const float* b1     = (const float*)d_in[10];
    const float* w2     = (const float*)d_in[11];
    const float* b2     = (const float*)d_in[12];
    const float* ln1_s  = (const float*)d_in[13];
    const float* ln1_b  = (const float*)d_in[14];
    const float* ln2_s  = (const float*)d_in[15];
    const float* ln2_b  = (const float*)d_in[16];
    const float* lnf_s  = (const float*)d_in[17];
    const float* lnf_b  = (const float*)d_in[18];
    float* out = (float*)d_out;

    float *px, *ph, *pq, *pk, *pv, *patt, *psc, *pff;
    cudaGetSymbolAddress((void**)&px,  g_x);
    cudaGetSymbolAddress((void**)&ph,  g_h);
    cudaGetSymbolAddress((void**)&pq,  g_q);
    cudaGetSymbolAddress((void**)&pk,  g_k);
    cudaGetSymbolAddress((void**)&pv,  g_v);
    cudaGetSymbolAddress((void**)&patt,g_att);
    cudaGetSymbolAddress((void**)&psc, g_scores);
    cudaGetSymbolAddress((void**)&pff, g_ff);

    te_embed_kernel<<<ROWS, 256>>>(ids, emb, pe);

    for (int l = 0; l < LL; l++) {
        const float* wq  = w_q + (long long)l * DD * DD;
        const float* wk  = w_k + (long long)l * DD * DD;
        const float* wv  = w_v + (long long)l * DD * DD;
        const float* wo  = w_o + (long long)l * DD * DD;
        const float* bo  = b_o + (long long)l * DD;
        const float* W1  = w1  + (long long)l * DD * FF;
        const float* B1  = b1  + (long long)l * FF;
        const float* W2  = w2  + (long long)l * FF * DD;
        const float* B2  = b2  + (long long)l * DD;

        // LN1
        te_ln_kernel<<<ROWS, 256>>>(px, ph, ln1_s + (long long)l*DD, ln1_b + (long long)l*DD);

        // Q, K, V projections: (2048,1024) @ (1024,1024)
        dim3 gProj(DD / BN, ROWS / BM, 1);
        te_mmgemm_kernel<false><<<gProj, 256>>>(ROWS, DD, DD, ph, DD, 0, wq, DD, 0,
                                                pq, DD, 0, nullptr, nullptr, 0, 0, 1.f, 0);
        te_mmgemm_kernel<false><<<gProj, 256>>>(ROWS, DD, DD, ph, DD, 0, wk, DD, 0,
                                                pk, DD, 0, nullptr, nullptr, 0, 0, 1.f, 0);
        te_mmgemm_kernel<false><<<gProj, 256>>>(ROWS, DD, DD, ph, DD, 0, wv, DD, 0,
                                                pv, DD, 0, nullptr, nullptr, 0, 0, 1.f, 0);

        // scores[b,h] = q_bh @ k_bh^T / 8 ;  per b, batch over heads (z)
        for (int b = 0; b < BB; b++) {
            dim3 gSc(SS / BN, SS / BM, HH);
            te_mmgemm_kernel<true><<<gSc, 256>>>(SS, SS, DKK,
                pq + (long long)b * SS * DD, DD, DKK,
                pk + (long long)b * SS * DD, DD, DKK,
                psc + (long long)b * HH * SS * SS, SS, (long long)SS * SS,
                nullptr, nullptr, 0, 0, 0.125f, 0);
        }

        te_softmax_kernel<<<BB * HH * SS, 256>>>(amask);

        // attn @ v : per b, batch over heads
        for (int b = 0; b < BB; b++) {
            dim3 gAv(1, SS / BM, HH);
            te_mmgemm_kernel<false><<<gAv, 256>>>(SS, DKK, SS,
                psc + (long long)b * HH * SS * SS, SS, (long long)SS * SS,
                pv + (long long)b * SS * DD, DD, DKK,
                patt + (long long)b * SS * DD, DD, DKK,
                nullptr, nullptr, 0, 0, 1.f, 0);
        }

        // Wo projection + bias + residual -> x
        te_mmgemm_kernel<false><<<gProj, 256>>>(ROWS, DD, DD, patt, DD, 0, wo, DD, 0,
                                                px, DD, 0, bo, px, DD, 0, 1.f, 0);

        // LN2
        te_ln_kernel<<<ROWS, 256>>>(px, ph, ln2_s + (long long)l*DD, ln2_b + (long long)l*DD);

        // FF1: relu(h @ W1 + B1)
        dim3 gF1(FF / BN, ROWS / BM, 1);
        te_mmgemm_kernel<false><<<gF1, 256>>>(ROWS, FF, DD, ph, DD, 0, W1, FF, 0,
                                              pff, FF, 0, B1, nullptr, 0, 0, 1.f, 1);
        // FF2: ff @ W2 + B2 + residual -> x
        dim3 gF2(DD / BN, ROWS / BM, 1);
        te_mmgemm_kernel<false><<<gF2, 256>>>(ROWS, DD, FF, pff, FF, 0, W2, DD, 0,
                                              px, DD, 0, B2, px, DD, 0, 1.f, 0);
    }

    // final LN -> out
    te_ln_kernel<<<ROWS, 256>>>(px, out, lnf_s, lnf_b);
}